// round 4
// baseline (speedup 1.0000x reference)
#include <cuda_runtime.h>
#include <cstdint>

#define KCH 4
#define INF 10
#define HH  20

// ---- packed f32x2 helpers (SASS FFMA2 path; only reachable via PTX) ----
__device__ __forceinline__ uint64_t pk2(float lo, float hi) {
    uint64_t d;
    asm("mov.b64 %0, {%1, %2};" : "=l"(d) : "r"(__float_as_uint(lo)), "r"(__float_as_uint(hi)));
    return d;
}
__device__ __forceinline__ uint64_t fma2(uint64_t a, uint64_t b, uint64_t c) {
    uint64_t d;
    asm("fma.rn.f32x2 %0, %1, %2, %3;" : "=l"(d) : "l"(a), "l"(b), "l"(c));
    return d;
}
__device__ __forceinline__ uint64_t add2(uint64_t a, uint64_t b) {
    uint64_t d;
    asm("add.rn.f32x2 %0, %1, %2;" : "=l"(d) : "l"(a), "l"(b));
    return d;
}
__device__ __forceinline__ float hadd2(uint64_t a) {
    uint32_t lo, hi;
    asm("mov.b64 {%0, %1}, %2;" : "=r"(lo), "=r"(hi) : "l"(a));
    return __uint_as_float(lo) + __uint_as_float(hi);
}

__device__ __forceinline__ float sigf(float v) {
    return __fdividef(1.0f, 1.0f + __expf(-v));
}
// NaN-safe fast tanh: exp argument always <= 0
__device__ __forceinline__ float tanhfast(float v) {
    float t = __expf(-2.0f * fabsf(v));
    float r = __fdividef(1.0f - t, 1.0f + t);
    return copysignf(r, v);
}

// dot of 6 packed pairs (12 floats): W rows padded to 16, cols 10..15 zero
__device__ __forceinline__ float dotW(const uint64_t* __restrict__ w, const uint64_t* xv2) {
    uint64_t acc = fma2(w[0], xv2[0], 0ull);
    #pragma unroll
    for (int t = 1; t < 6; t++) acc = fma2(w[t], xv2[t], acc);
    return hadd2(acc);
}
// dot of 10 packed pairs (20 floats): U rows, stride 20 floats (80B, 8B-aligned)
__device__ __forceinline__ float dotU(const uint64_t* __restrict__ u, const uint64_t* hv2) {
    uint64_t acc = fma2(u[0], hv2[0], 0ull);
    #pragma unroll
    for (int t = 1; t < 10; t++) acc = fma2(u[t], hv2[t], acc);
    return hadd2(acc);
}

__global__ __launch_bounds__(256)
void treelstm_kernel(const float* __restrict__ x,
                     const float* __restrict__ hch,
                     const float* __restrict__ cch,
                     const float* __restrict__ Wiou_w, const float* __restrict__ Wiou_b,
                     const float* __restrict__ Uiou_w, const float* __restrict__ Uiou_b,
                     const float* __restrict__ Wf_w,   const float* __restrict__ Wf_b,
                     const float* __restrict__ Uf_w,   const float* __restrict__ Uf_b,
                     float* __restrict__ out_h, float* __restrict__ out_c,
                     int n_nodes)
{
    // Weights staged in shared. W-matrices (in=10) padded to row stride 16 with
    // zeros so dots are aligned packed-pair ops. All rows 8B-aligned.
    __shared__ __align__(16) float sWf[HH * 16];
    __shared__ __align__(16) float sUf[HH * HH];
    __shared__ __align__(16) float sWiou[3 * HH * 16];
    __shared__ __align__(16) float sUiou[3 * HH * HH];
    __shared__ float sWfb[HH], sUfb[HH];
    __shared__ float sWioub[3 * HH], sUioub[3 * HH];

    const int tid = threadIdx.x;

    for (int i = tid; i < HH * 16; i += blockDim.x) {
        int r = i >> 4, c = i & 15;
        sWf[i] = (c < INF) ? Wf_w[r * INF + c] : 0.0f;
    }
    for (int i = tid; i < 3 * HH * 16; i += blockDim.x) {
        int r = i >> 4, c = i & 15;
        sWiou[i] = (c < INF) ? Wiou_w[r * INF + c] : 0.0f;
    }
    for (int i = tid; i < HH * HH; i += blockDim.x) sUf[i] = Uf_w[i];
    for (int i = tid; i < 3 * HH * HH; i += blockDim.x) sUiou[i] = Uiou_w[i];
    if (tid < HH)     { sWfb[tid] = Wf_b[tid];     sUfb[tid] = Uf_b[tid]; }
    if (tid < 3 * HH) { sWioub[tid] = Wiou_b[tid]; sUioub[tid] = Uiou_b[tid]; }
    __syncthreads();

    const int n = blockIdx.x * blockDim.x + tid;
    if (n >= n_nodes) return;

    // x row (40B) -> 6 packed pairs, zero-padded
    uint64_t xv2[6];
    {
        const float2* xp = (const float2*)(x + (size_t)n * INF);
        #pragma unroll
        for (int q = 0; q < 5; q++) { float2 v = xp[q]; xv2[q] = pk2(v.x, v.y); }
        xv2[5] = 0ull;
    }

    // fx = W_f x + b_f   [20]
    float fx[HH];
    #pragma unroll
    for (int j = 0; j < HH; j++)
        fx[j] = dotW((const uint64_t*)&sWf[j * 16], xv2) + sWfb[j];

    uint64_t hsum2[10];
    float cacc[HH];
    #pragma unroll
    for (int t = 0; t < 10; t++) hsum2[t] = 0ull;
    #pragma unroll
    for (int j = 0; j < HH; j++) cacc[j] = 0.0f;

    // Children: cacc += sigmoid(fx + U_f h_k + b_u) * c_k ; hsum += h_k
    #pragma unroll
    for (int k = 0; k < KCH; k++) {
        uint64_t hk2[10];
        const float4* hp = (const float4*)(hch + ((size_t)k * n_nodes + n) * HH);
        #pragma unroll
        for (int q = 0; q < 5; q++) {
            float4 v = hp[q];
            hk2[2*q]   = pk2(v.x, v.y);
            hk2[2*q+1] = pk2(v.z, v.w);
        }
        #pragma unroll
        for (int t = 0; t < 10; t++) hsum2[t] = add2(hsum2[t], hk2[t]);

        const float4* cp = (const float4*)(cch + ((size_t)k * n_nodes + n) * HH);
        #pragma unroll
        for (int q = 0; q < 5; q++) {
            float4 cv = cp[q];
            float cvv[4] = {cv.x, cv.y, cv.z, cv.w};
            #pragma unroll
            for (int r = 0; r < 4; r++) {
                const int j = 4 * q + r;
                float a = dotU((const uint64_t*)&sUf[j * HH], hk2) + sUfb[j] + fx[j];
                cacc[j] += sigf(a) * cvv[r];
            }
        }
    }

    // iou = W_iou x + b_w + U_iou hsum + K*b_u ; gates, outputs
    float* oh = out_h + (size_t)n * HH;
    float* oc = out_c + (size_t)n * HH;
    #pragma unroll
    for (int q = 0; q < 5; q++) {
        float res_h[4], res_c[4];
        #pragma unroll
        for (int r = 0; r < 4; r++) {
            const int j = 4 * q + r;
            float acc_i = sWioub[j]        + 4.0f * sUioub[j]
                        + dotW((const uint64_t*)&sWiou[(j)        * 16], xv2)
                        + dotU((const uint64_t*)&sUiou[(j)        * HH], hsum2);
            float acc_o = sWioub[j + HH]   + 4.0f * sUioub[j + HH]
                        + dotW((const uint64_t*)&sWiou[(j + HH)   * 16], xv2)
                        + dotU((const uint64_t*)&sUiou[(j + HH)   * HH], hsum2);
            float acc_u = sWioub[j + 2*HH] + 4.0f * sUioub[j + 2*HH]
                        + dotW((const uint64_t*)&sWiou[(j + 2*HH) * 16], xv2)
                        + dotU((const uint64_t*)&sUiou[(j + 2*HH) * HH], hsum2);

            float cval = sigf(acc_i) * tanhfast(acc_u) + cacc[j];
            float hval = sigf(acc_o) * tanhfast(cval);
            res_c[r] = cval;
            res_h[r] = hval;
        }
        ((float4*)oh)[q] = make_float4(res_h[0], res_h[1], res_h[2], res_h[3]);
        ((float4*)oc)[q] = make_float4(res_c[0], res_c[1], res_c[2], res_c[3]);
    }
}

extern "C" void kernel_launch(void* const* d_in, const int* in_sizes, int n_in,
                              void* d_out, int out_size)
{
    const float* x      = (const float*)d_in[0];
    const float* hch    = (const float*)d_in[1];
    const float* cch    = (const float*)d_in[2];
    const float* Wiou_w = (const float*)d_in[3];
    const float* Wiou_b = (const float*)d_in[4];
    const float* Uiou_w = (const float*)d_in[5];
    const float* Uiou_b = (const float*)d_in[6];
    const float* Wf_w   = (const float*)d_in[7];
    const float* Wf_b   = (const float*)d_in[8];
    const float* Uf_w   = (const float*)d_in[9];
    const float* Uf_b   = (const float*)d_in[10];

    const int n_nodes = in_sizes[0] / INF;

    float* out_h = (float*)d_out;
    float* out_c = out_h + (size_t)n_nodes * HH;

    const int threads = 256;
    const int blocks = (n_nodes + threads - 1) / threads;

    treelstm_kernel<<<blocks, threads>>>(x, hch, cch,
                                         Wiou_w, Wiou_b, Uiou_w, Uiou_b,
                                         Wf_w, Wf_b, Uf_w, Uf_b,
                                         out_h, out_c, n_nodes);
}